// round 16
// baseline (speedup 1.0000x reference)
#include <cuda_runtime.h>
#include <cuda_fp16.h>
#include <math.h>
#include <stdint.h>

#define B_   4
#define S_   1024
#define D_   1024
#define H_   16
#define HD_  64
#define FF_  4096
#define NT   (B_*S_)
#define NEGV (-1e9f)

// ---------------- scratch -------------------------------------------------
__device__ int   g_kidx[B_*H_*S_];
__device__ int   g_kcnt[B_*H_];

__device__ __half g_wqkv16[3*D_*D_];
__device__ __half g_wo16  [D_*D_];
__device__ __half g_w116  [FF_*D_];
__device__ __half g_w216  [D_*FF_];
__device__ __half g_x16   [NT*D_];
__device__ __half g_qkv16 [NT*3*D_];
__device__ __half g_ctx16 [NT*D_];
__device__ __half g_h16   [NT*D_];
__device__ __half g_f116  [NT*FF_];
__device__ __half g_attn16[NT*D_];
__device__ __half g_f216  [NT*D_];

// ================= helpers =================================================
__device__ __forceinline__ uint32_t smem_u32(const void* p) {
    uint32_t a;
    asm("{ .reg .u64 t; cvta.to.shared.u64 t, %1; cvt.u32.u64 %0, t; }"
        : "=r"(a) : "l"(p));
    return a;
}
__device__ __forceinline__ void cp16(uint32_t dst, const void* src) {
    asm volatile("cp.async.cg.shared.global [%0], [%1], 16;" :: "r"(dst), "l"(src));
}
#define CP_COMMIT() asm volatile("cp.async.commit_group;" ::: "memory")
#define CP_WAIT0()  asm volatile("cp.async.wait_group 0;" ::: "memory")
#define CP_WAIT1()  asm volatile("cp.async.wait_group 1;" ::: "memory")

#define LDSM4(r0,r1,r2,r3,addr) \
    asm volatile("ldmatrix.sync.aligned.m8n8.x4.shared.b16 {%0,%1,%2,%3}, [%4];" \
        : "=r"(r0), "=r"(r1), "=r"(r2), "=r"(r3) : "r"(addr))
#define LDSM4T(r0,r1,r2,r3,addr) \
    asm volatile("ldmatrix.sync.aligned.m8n8.x4.trans.shared.b16 {%0,%1,%2,%3}, [%4];" \
        : "=r"(r0), "=r"(r1), "=r"(r2), "=r"(r3) : "r"(addr))

__device__ __forceinline__ void mma_f16(
    float& d0, float& d1, float& d2, float& d3,
    uint32_t a0, uint32_t a1, uint32_t a2, uint32_t a3,
    uint32_t b0, uint32_t b1)
{
    asm volatile(
        "mma.sync.aligned.m16n8k16.row.col.f32.f16.f16.f32 "
        "{%0,%1,%2,%3}, {%4,%5,%6,%7}, {%8,%9}, {%0,%1,%2,%3};"
        : "+f"(d0), "+f"(d1), "+f"(d2), "+f"(d3)
        : "r"(a0), "r"(a1), "r"(a2), "r"(a3), "r"(b0), "r"(b1));
}

__device__ __forceinline__ uint32_t pack_h2(float a, float b) {
    __half2 h = __floats2half2_rn(a, b);
    return *(uint32_t*)&h;
}

// ---------------- fused fp32 -> fp16 convert -------------------------------
#define CVT_C0 (3*D_*D_)
#define CVT_C1 (CVT_C0 + D_*D_)
#define CVT_C2 (CVT_C1 + FF_*D_)
#define CVT_C3 (CVT_C2 + D_*FF_)
#define CVT_C4 (CVT_C3 + NT*D_)
#define CVT_BLOCKS (CVT_C4 / 4 / 256)

__global__ void __launch_bounds__(256) cvt_all_kernel(
    const float* __restrict__ Wqkv, const float* __restrict__ Wo,
    const float* __restrict__ W1,   const float* __restrict__ W2,
    const float* __restrict__ x,
    __half* __restrict__ wq16, __half* __restrict__ wo16,
    __half* __restrict__ w116, __half* __restrict__ w216,
    __half* __restrict__ x16)
{
    int i = (blockIdx.x * 256 + threadIdx.x) * 4;
    const float* in; __half* out; int base;
    if      (i < CVT_C0) { in = Wqkv; out = wq16; base = 0; }
    else if (i < CVT_C1) { in = Wo;   out = wo16; base = CVT_C0; }
    else if (i < CVT_C2) { in = W1;   out = w116; base = CVT_C1; }
    else if (i < CVT_C3) { in = W2;   out = w216; base = CVT_C2; }
    else                 { in = x;    out = x16;  base = CVT_C3; }
    i -= base;
    float4 v = *(const float4*)(in + i);
    *(uint32_t*)(out + i)     = pack_h2(v.x, v.y);
    *(uint32_t*)(out + i + 2) = pack_h2(v.z, v.w);
}

// ---------------- HMMA fp16 GEMM: C = A * B^T + bias -----------------------
// 128x128 CTA tile, BK=64, 256 threads (8 warps of 64x32), 2 CTAs/SM.
// 2-slot double buffer: wait -> barrier -> prefetch(next) -> compute.
#define TSTRIDE   144                   // 128 B data + 16 B pad per row
#define TMAT      (128 * TSTRIDE)       // 18432 B
#define TSTAGE    (2 * TMAT)            // 36864 B
#define GEMM_SMEM (2 * TSTAGE)          // 73728 B

template<int RELU, int OUT>
__global__ void __launch_bounds__(256, 2) gemm_mma(
    const __half* __restrict__ A, const __half* __restrict__ Bm,
    const float* __restrict__ bias, float* __restrict__ C,
    __half* __restrict__ Ch,
    int M, int N, int K)
{
    extern __shared__ char smem[];
    const uint32_t sbase = smem_u32(smem);
    const int tid  = threadIdx.x;
    const int wid  = tid >> 5;
    const int lane = tid & 31;
    const int row0 = blockIdx.y * 128;
    const int col0 = blockIdx.x * 128;
    const int wm   = wid & 1;
    const int wn   = wid >> 1;

    const int l_mat = lane >> 3, l_r = lane & 7;
    const int frag_row = l_r + (l_mat & 1) * 8;
    const int frag_kb  = (l_mat >> 1) * 16;

    // cp.async addressing: 8 chunks of 16B per 128B row; 32 rows per pass.
    const int cp_row = tid >> 3;        // 0..31
    const int cp_c   = tid & 7;         // 0..7
    const __half* pA = A  + (size_t)(row0 + cp_row) * K + cp_c * 8;
    const __half* pB = Bm + (size_t)(col0 + cp_row) * K + cp_c * 8;
    const uint32_t sA0 = sbase + cp_row * TSTRIDE + cp_c * 16;
    const uint32_t sB0 = sA0 + TMAT;
    const size_t rstep = (size_t)32 * K;

    float acc[4][4][4];
    #pragma unroll
    for (int i = 0; i < 4; i++)
        #pragma unroll
        for (int j = 0; j < 4; j++)
            #pragma unroll
            for (int r = 0; r < 4; r++) acc[i][j][r] = 0.f;

    const int nstage = K >> 6;

    // prologue: stage 0 into slot 0
    #pragma unroll
    for (int p = 0; p < 4; p++) {
        cp16(sA0 + p * 32 * TSTRIDE, pA + p * rstep);
        cp16(sB0 + p * 32 * TSTRIDE, pB + p * rstep);
    }
    CP_COMMIT();

    for (int s = 0; s < nstage; s++) {
        CP_WAIT0();          // stage s landed
        __syncthreads();     // all warps done reading the other slot

        if (s + 1 < nstage) {
            const uint32_t off = ((s + 1) & 1) * TSTAGE;
            const int k0 = (s + 1) << 6;
            #pragma unroll
            for (int p = 0; p < 4; p++) {
                cp16(sA0 + off + p * 32 * TSTRIDE, pA + p * rstep + k0);
                cp16(sB0 + off + p * 32 * TSTRIDE, pB + p * rstep + k0);
            }
            CP_COMMIT();
        }

        const uint32_t buf = sbase + (s & 1) * TSTAGE;
        const uint32_t bA = buf;
        const uint32_t bB = buf + TMAT;

        #pragma unroll
        for (int ks = 0; ks < 4; ks++) {
            const int kb = ks * 32 + frag_kb;

            uint32_t a[4][4], b[2][4];
            #pragma unroll
            for (int mi = 0; mi < 4; mi++) {
                uint32_t ra = (wm * 64 + mi * 16 + frag_row) * TSTRIDE + kb;
                LDSM4(a[mi][0], a[mi][1], a[mi][2], a[mi][3], bA + ra);
            }
            #pragma unroll
            for (int nb = 0; nb < 2; nb++) {
                uint32_t rb = (wn * 32 + nb * 16 + frag_row) * TSTRIDE + kb;
                LDSM4(b[nb][0], b[nb][1], b[nb][2], b[nb][3], bB + rb);
            }

            #pragma unroll
            for (int mi = 0; mi < 4; mi++)
                #pragma unroll
                for (int ni = 0; ni < 4; ni++) {
                    const int nb = ni >> 1, no = ni & 1;
                    mma_f16(acc[mi][ni][0], acc[mi][ni][1],
                            acc[mi][ni][2], acc[mi][ni][3],
                            a[mi][0], a[mi][1], a[mi][2], a[mi][3],
                            b[nb][no], b[nb][no + 2]);
                }
        }
    }

    const int g8  = lane >> 2;
    const int tig = lane & 3;
    #pragma unroll
    for (int mi = 0; mi < 4; mi++) {
        #pragma unroll
        for (int ni = 0; ni < 4; ni++) {
            int col = col0 + wn * 32 + ni * 8 + tig * 2;
            float2 bs = *(const float2*)(bias + col);
            int r0 = row0 + wm * 64 + mi * 16 + g8;
            float2 v0 = { acc[mi][ni][0] + bs.x, acc[mi][ni][1] + bs.y };
            float2 v1 = { acc[mi][ni][2] + bs.x, acc[mi][ni][3] + bs.y };
            if (RELU) {
                v0.x = fmaxf(v0.x, 0.f); v0.y = fmaxf(v0.y, 0.f);
                v1.x = fmaxf(v1.x, 0.f); v1.y = fmaxf(v1.y, 0.f);
            }
            if (OUT == 0) {
                *(float2*)(C + (size_t)r0 * N + col)       = v0;
                *(float2*)(C + (size_t)(r0 + 8) * N + col) = v1;
            } else {
                *(uint32_t*)(Ch + (size_t)r0 * N + col)       = pack_h2(v0.x, v0.y);
                *(uint32_t*)(Ch + (size_t)(r0 + 8) * N + col) = pack_h2(v1.x, v1.y);
            }
        }
    }
}

// ---------------- mask compaction (with inline dtype probe) ----------------
__device__ __forceinline__ float mask_val_m(const void* mp, int idx, int mode) {
    if (mode == 0) return ((const int*)mp)[idx] ? 1.f : 0.f;
    if (mode == 1) return ((const unsigned char*)mp)[idx] ? 1.f : 0.f;
    return ((const float*)mp)[idx];
}

__global__ void __launch_bounds__(256) compact_mask_kernel(
    const void* __restrict__ mask, int* __restrict__ kidx,
    int* __restrict__ kcnt)
{
    const int bh  = blockIdx.x;
    const int tid = threadIdx.x;
    const int lane = tid & 31, wid = tid >> 5;
    __shared__ int wsum[8];
    __shared__ int stotal;
    __shared__ int smode;

    {
        __shared__ int f3f, foff;
        if (tid == 0) { f3f = 0; foff = 0; }
        __syncthreads();
        const unsigned char* m8 = (const unsigned char*)mask;
        int l3f = 0, loff = 0;
        for (int i = tid; i < 4096; i += 256) {
            unsigned char v = m8[i];
            if (v == 0x3f) l3f = 1;
            else if (v && (i & 3)) loff = 1;
        }
        if (l3f)  atomicOr(&f3f, 1);
        if (loff) atomicOr(&foff, 1);
        __syncthreads();
        if (tid == 0) smode = f3f ? 2 : (foff ? 1 : 0);
        __syncthreads();
    }
    const int mode = smode;

    int v[4], c = 0;
    #pragma unroll
    for (int j = 0; j < 4; j++) {
        v[j] = (mask_val_m(mask, bh * S_ + tid * 4 + j, mode) > 0.5f) ? 1 : 0;
        c += v[j];
    }
    int sc = c;
    #pragma unroll
    for (int o = 1; o < 32; o <<= 1) {
        int n = __shfl_up_sync(0xffffffffu, sc, o);
        if (lane >= o) sc += n;
    }
    if (lane == 31) wsum[wid] = sc;
    __syncthreads();
    if (tid == 0) {
        int acc = 0;
        #pragma unroll
        for (int i = 0; i < 8; i++) { int t = wsum[i]; wsum[i] = acc; acc += t; }
        stotal = acc;
    }
    __syncthreads();
    int off = sc - c + wsum[wid];
    #pragma unroll
    for (int j = 0; j < 4; j++)
        if (v[j]) kidx[bh * S_ + off++] = tid * 4 + j;
    int total = stotal;
    if (tid == 0) kcnt[bh] = total;
    for (int i = total + tid; i < S_; i += 256) kidx[bh * S_ + i] = 0;
}

// ---------------- flash attention (compacted keys, 3-stage pipeline) -------
#define ASTRIDE 144
#define KVMAT   (64 * ASTRIDE)
#define KVSTAGE (2 * KVMAT)
#define SMEM_ATTN (128 * ASTRIDE + 3 * KVSTAGE)
#define LOG2E_SC 0.18033688f

__device__ __forceinline__ void kv_prefetch(
    uint32_t sKV, int slot, int jb, int tid, int rowbase, int h,
    const __half* QKV, const int* __restrict__ idx)
{
    const uint32_t base = sKV + slot * KVSTAGE;
    const int r  = tid >> 2;
    const int c0 = tid & 3;
    const int token = __ldg(idx + jb * 64 + r);
    const size_t go = (size_t)(rowbase + token) * (3 * D_) + h * HD_;
    const __half* srcs[2] = { QKV + go + D_, QKV + go + 2 * D_ };
    #pragma unroll
    for (int m = 0; m < 2; m++) {
        const uint32_t mb = base + m * KVMAT + r * ASTRIDE;
        cp16(mb + c0 * 16,       srcs[m] + c0 * 8);
        cp16(mb + (c0 + 4) * 16, srcs[m] + (c0 + 4) * 8);
    }
}

__global__ void __launch_bounds__(256, 2) attn_mma_kernel(
    const __half* __restrict__ QKV,
    const int* __restrict__ kidx, const int* __restrict__ kcnt,
    __half* __restrict__ Cc)
{
    const int it = blockIdx.x, h = blockIdx.y, b = blockIdx.z;
    const int bh = b * H_ + h;
    extern __shared__ char sm8[];
    const uint32_t sb = smem_u32(sm8);
    const uint32_t sQ  = sb;
    const uint32_t sKV = sb + 128 * ASTRIDE;

    const int tid = threadIdx.x, w = tid >> 5, lane = tid & 31;
    const int i0 = it * 128, rowbase = b * S_;
    const int frag_row = (lane & 7) + ((lane >> 3) & 1) * 8;
    const int frag_kb  = (lane >> 4) * 16;
    const int pcol = (lane & 3) * 2;

    const int cnt = kcnt[bh];
    const int nt  = (cnt + 63) >> 6;
    const int* idx = kidx + bh * S_;

    {
        int r = tid >> 1;
        const size_t go = (size_t)(rowbase + i0 + r) * (3 * D_) + h * HD_;
        #pragma unroll
        for (int c = 0; c < 4; c++) {
            int ch = (tid & 1) * 4 + c;
            cp16(sQ + r * ASTRIDE + ch * 16, QKV + go + ch * 8);
        }
    }
    kv_prefetch(sKV, 0, 0, tid, rowbase, h, QKV, idx);
    CP_COMMIT();
    if (nt > 1) kv_prefetch(sKV, 1, 1, tid, rowbase, h, QKV, idx);
    CP_COMMIT();

    float m_run[2] = { -3.0e38f, -3.0e38f };
    float l_run[2] = { 0.f, 0.f };
    float o[8][4];
    #pragma unroll
    for (int d = 0; d < 8; d++)
        #pragma unroll
        for (int r = 0; r < 4; r++) o[d][r] = 0.f;

    int slot = 0, islot = 2;
    for (int jb = 0; jb < nt; jb++) {
        CP_WAIT1();
        __syncthreads();

        if (jb + 2 < nt)
            kv_prefetch(sKV, islot, jb + 2, tid, rowbase, h, QKV, idx);
        CP_COMMIT();

        const uint32_t kvb = sKV + slot * KVSTAGE;
        const uint32_t bK = kvb, bV = kvb + KVMAT;

        float s[8][4];
        #pragma unroll
        for (int t = 0; t < 8; t++)
            #pragma unroll
            for (int r = 0; r < 4; r++) s[t][r] = 0.f;

        #pragma unroll
        for (int kk = 0; kk < 4; kk++) {
            uint32_t q0, q1, q2, q3;
            uint32_t qa = (w * 16 + frag_row) * ASTRIDE + kk * 32 + frag_kb;
            LDSM4(q0, q1, q2, q3, sQ + qa);
            #pragma unroll
            for (int nb = 0; nb < 4; nb++) {
                uint32_t k0, k1, k2, k3;
                uint32_t ad = (nb * 16 + frag_row) * ASTRIDE + kk * 32 + frag_kb;
                LDSM4(k0, k1, k2, k3, bK + ad);
                const int t0 = nb * 2, t1 = nb * 2 + 1;
                mma_f16(s[t0][0], s[t0][1], s[t0][2], s[t0][3],
                        q0, q1, q2, q3, k0, k2);
                mma_f16(s[t1][0], s[t1][1], s[t1][2], s[t1][3],
                        q0, q1, q2, q3, k1, k3);
            }
        }

        #pragma unroll
        for (int t = 0; t < 8; t++) {
            int p = jb * 64 + t * 8 + pcol;
            bool v0 = p < cnt, v1 = p + 1 < cnt;
            s[t][0] = v0 ? s[t][0] * LOG2E_SC : NEGV;
            s[t][1] = v1 ? s[t][1] * LOG2E_SC : NEGV;
            s[t][2] = v0 ? s[t][2] * LOG2E_SC : NEGV;
            s[t][3] = v1 ? s[t][3] * LOG2E_SC : NEGV;
        }

        float mx0 = -3.0e38f, mx1 = -3.0e38f;
        #pragma unroll
        for (int t = 0; t < 8; t++) {
            mx0 = fmaxf(mx0, fmaxf(s[t][0], s[t][1]));
            mx1 = fmaxf(mx1, fmaxf(s[t][2], s[t][3]));
        }
        mx0 = fmaxf(mx0, __shfl_xor_sync(0xffffffffu, mx0, 1));
        mx0 = fmaxf(mx0, __shfl_xor_sync(0xffffffffu, mx0, 2));
        mx1 = fmaxf(mx1, __shfl_xor_sync(0xffffffffu, mx1, 1));
        mx1 = fmaxf(mx1, __shfl_xor_sync(0xffffffffu, mx1, 2));
        float nm0 = fmaxf(m_run[0], mx0), nm1 = fmaxf(m_run[1], mx1);
        float corr0 = exp2f(m_run[0] - nm0), corr1 = exp2f(m_run[1] - nm1);
        m_run[0] = nm0; m_run[1] = nm1;

        float sum0 = 0.f, sum1 = 0.f;
        #pragma unroll
        for (int t = 0; t < 8; t++) {
            s[t][0] = exp2f(s[t][0] - nm0); sum0 += s[t][0];
            s[t][1] = exp2f(s[t][1] - nm0); sum0 += s[t][1];
            s[t][2] = exp2f(s[t][2] - nm1); sum1 += s[t][2];
            s[t][3] = exp2f(s[t][3] - nm1); sum1 += s[t][3];
        }
        sum0 += __shfl_xor_sync(0xffffffffu, sum0, 1);
        sum0 += __shfl_xor_sync(0xffffffffu, sum0, 2);
        sum1 += __shfl_xor_sync(0xffffffffu, sum1, 1);
        sum1 += __shfl_xor_sync(0xffffffffu, sum1, 2);
        l_run[0] = l_run[0] * corr0 + sum0;
        l_run[1] = l_run[1] * corr1 + sum1;

        #pragma unroll
        for (int d = 0; d < 8; d++) {
            o[d][0] *= corr0; o[d][1] *= corr0;
            o[d][2] *= corr1; o[d][3] *= corr1;
        }

        #pragma unroll
        for (int kk = 0; kk < 4; kk++) {
            const int t0 = kk * 2, t1 = kk * 2 + 1;
            uint32_t pa[4];
            pa[0] = pack_h2(s[t0][0], s[t0][1]);
            pa[1] = pack_h2(s[t0][2], s[t0][3]);
            pa[2] = pack_h2(s[t1][0], s[t1][1]);
            pa[3] = pack_h2(s[t1][2], s[t1][3]);

            const uint32_t vrow =
                (kk * 16 + ((lane >> 3) & 1) * 8 + (lane & 7)) * ASTRIDE +
                (lane >> 4) * 16;
            #pragma unroll
            for (int qd = 0; qd < 4; qd++) {
                uint32_t v0, v1, v2, v3;
                LDSM4T(v0, v1, v2, v3, bV + vrow + qd * 32);
                const int d0 = qd * 2, d1 = qd * 2 + 1;
                mma_f16(o[d0][0], o[d0][1], o[d0][2], o[d0][3],
                        pa[0], pa[1], pa[2], pa[3], v0, v1);
                mma_f16(o[d1][0], o[d1][1], o[d1][2], o[d1][3],
                        pa[0], pa[1], pa[2], pa[3], v2, v3);
            }
        }
        slot  = (slot  == 2) ? 0 : slot + 1;
        islot = (islot == 2) ? 0 : islot + 1;
    }

    const float inv0 = 1.f / l_run[0], inv1 = 1.f / l_run[1];
    const int tok0 = rowbase + i0 + w * 16 + (lane >> 2);
    #pragma unroll
    for (int d = 0; d < 8; d++) {
        int col = h * HD_ + d * 8 + (lane & 3) * 2;
        *(uint32_t*)(Cc + (size_t)tok0 * D_ + col) =
            pack_h2(o[d][0] * inv0, o[d][1] * inv0);
        *(uint32_t*)(Cc + (size_t)(tok0 + 8) * D_ + col) =
            pack_h2(o[d][2] * inv1, o[d][3] * inv1);
    }
}

// ---------------- residual + LayerNorm (all-fp16 in; fp16 or fp32 out) -----
template<int OUTF32>
__global__ void __launch_bounds__(256) ln_residual_kernel(
    const __half* __restrict__ a, const __half* __restrict__ res,
    const float* __restrict__ gamma, const float* __restrict__ beta,
    float* __restrict__ out, __half* __restrict__ oh)
{
    const int row = blockIdx.x;
    const int tid = threadIdx.x;
    const __half* pa = a   + (size_t)row * D_ + tid * 4;
    const __half* pr = res + (size_t)row * D_ + tid * 4;

    __half2 a01 = *(const __half2*)(pa);
    __half2 a23 = *(const __half2*)(pa + 2);
    __half2 r01 = *(const __half2*)(pr);
    __half2 r23 = *(const __half2*)(pr + 2);
    float v[4];
    v[0] = __half2float(__low2half(a01))  + __half2float(__low2half(r01));
    v[1] = __half2float(__high2half(a01)) + __half2float(__high2half(r01));
    v[2] = __half2float(__low2half(a23))  + __half2float(__low2half(r23));
    v[3] = __half2float(__high2half(a23)) + __half2float(__high2half(r23));

    float sum = v[0] + v[1] + v[2] + v[3];
    float sq  = v[0]*v[0] + v[1]*v[1] + v[2]*v[2] + v[3]*v[3];
    #pragma unroll
    for (int o2 = 16; o2; o2 >>= 1) {
        sum += __shfl_xor_sync(0xffffffffu, sum, o2);
        sq  += __shfl_xor_sync(0xffffffffu, sq,  o2);
    }
    __shared__ float sh1[8], sh2[8];
    __shared__ float smean, srstd;
    if ((tid & 31) == 0) { sh1[tid >> 5] = sum; sh2[tid >> 5] = sq; }
    __syncthreads();
    if (tid == 0) {
        float s = 0.f, s2 = 0.f;
        #pragma unroll
        for (int i = 0; i < 8; i++) { s += sh1[i]; s2 += sh2[i]; }
        float mean = s * (1.f / D_);
        float var  = s2 * (1.f / D_) - mean * mean;
        smean = mean;
        srstd = rsqrtf(var + 1e-12f);
    }
    __syncthreads();
    float mean = smean, rstd = srstd;
    const int c0 = tid * 4;
    float4 gm = *(const float4*)(gamma + c0);
    float4 bt = *(const float4*)(beta + c0);
    float r0 = gm.x * (v[0] - mean) * rstd + bt.x;
    float r1 = gm.y * (v[1] - mean) * rstd + bt.y;
    float r2 = gm.z * (v[2] - mean) * rstd + bt.z;
    float r3 = gm.w * (v[3] - mean) * rstd + bt.w;
    if (OUTF32) {
        float4 o4 = { r0, r1, r2, r3 };
        *(float4*)(out + (size_t)row * D_ + c0) = o4;
    } else {
        *(uint32_t*)(oh + (size_t)row * D_ + c0)     = pack_h2(r0, r1);
        *(uint32_t*)(oh + (size_t)row * D_ + c0 + 2) = pack_h2(r2, r3);
    }
}

// ---------------- launch ---------------------------------------------------
extern "C" void kernel_launch(void* const* d_in, const int* in_sizes, int n_in,
                              void* d_out, int out_size)
{
    const float* x    = (const float*)d_in[0];
    const void*  mask = d_in[1];
    const float* Wqkv = (const float*)d_in[2];
    const float* bqkv = (const float*)d_in[3];
    const float* Wo   = (const float*)d_in[4];
    const float* bo   = (const float*)d_in[5];
    const float* W1   = (const float*)d_in[6];
    const float* b1   = (const float*)d_in[7];
    const float* W2   = (const float*)d_in[8];
    const float* b2   = (const float*)d_in[9];
    const float* g1   = (const float*)d_in[10];
    const float* be1  = (const float*)d_in[11];
    const float* g2   = (const float*)d_in[12];
    const float* be2  = (const float*)d_in[13];
    float* out = (float*)d_out;

    int *kidx, *kcnt;
    cudaGetSymbolAddress((void**)&kidx, g_kidx);
    cudaGetSymbolAddress((void**)&kcnt, g_kcnt);

    __half *wq16, *wo16, *w116, *w216, *x16, *qkv16, *ctx16, *h16, *f116;
    __half *attn16, *f216;
    cudaGetSymbolAddress((void**)&wq16, g_wqkv16);
    cudaGetSymbolAddress((void**)&wo16, g_wo16);
    cudaGetSymbolAddress((void**)&w116, g_w116);
    cudaGetSymbolAddress((void**)&w216, g_w216);
    cudaGetSymbolAddress((void**)&x16,  g_x16);
    cudaGetSymbolAddress((void**)&qkv16, g_qkv16);
    cudaGetSymbolAddress((void**)&ctx16, g_ctx16);
    cudaGetSymbolAddress((void**)&h16,  g_h16);
    cudaGetSymbolAddress((void**)&f116, g_f116);
    cudaGetSymbolAddress((void**)&attn16, g_attn16);
    cudaGetSymbolAddress((void**)&f216, g_f216);

    cudaFuncSetAttribute(attn_mma_kernel,
                         cudaFuncAttributeMaxDynamicSharedMemorySize, SMEM_ATTN);
    cudaFuncSetAttribute(gemm_mma<0,1>,
                         cudaFuncAttributeMaxDynamicSharedMemorySize, GEMM_SMEM);
    cudaFuncSetAttribute(gemm_mma<1,1>,
                         cudaFuncAttributeMaxDynamicSharedMemorySize, GEMM_SMEM);

    // 1: per-(b,h) key compaction (with inline dtype probe)
    compact_mask_kernel<<<B_ * H_, 256>>>(mask, kidx, kcnt);

    // 2: all converts in one launch
    cvt_all_kernel<<<CVT_BLOCKS, 256>>>(Wqkv, Wo, W1, W2, x,
                                        wq16, wo16, w116, w216, x16);

    // 3: qkv = x @ Wqkv^T + bqkv -> fp16
    gemm_mma<0,1><<<dim3(3 * D_ / 128, NT / 128), 256, GEMM_SMEM>>>(
        x16, wq16, bqkv, nullptr, qkv16, NT, 3 * D_, D_);

    // 4: attention over compacted keys -> ctx fp16
    attn_mma_kernel<<<dim3(S_ / 128, H_, B_), 256, SMEM_ATTN>>>(
        qkv16, kidx, kcnt, ctx16);

    // 5: attn_out = ctx @ Wo^T + bo -> fp16
    gemm_mma<0,1><<<dim3(D_ / 128, NT / 128), 256, GEMM_SMEM>>>(
        ctx16, wo16, bo, nullptr, attn16, NT, D_, D_);

    // 6: h = LN1(attn_out + x) -> fp16 only
    ln_residual_kernel<0><<<NT, 256>>>(attn16, x16, g1, be1, nullptr, h16);

    // 7: f1 = relu(h @ W1^T + b1) -> fp16
    gemm_mma<1,1><<<dim3(FF_ / 128, NT / 128), 256, GEMM_SMEM>>>(
        h16, w116, b1, nullptr, f116, NT, FF_, D_);

    // 8: f2 = f1 @ W2^T + b2 -> fp16
    gemm_mma<0,1><<<dim3(D_ / 128, NT / 128), 256, GEMM_SMEM>>>(
        f116, w216, b2, nullptr, f216, NT, D_, FF_);

    // 9: out = LN2(f2 + h) -> fp32
    ln_residual_kernel<1><<<NT, 256>>>(f216, h16, g2, be2, out, nullptr);
}

// round 17
// speedup vs baseline: 1.0166x; 1.0166x over previous
#include <cuda_runtime.h>
#include <cuda_fp16.h>
#include <math.h>
#include <stdint.h>

#define B_   4
#define S_   1024
#define D_   1024
#define H_   16
#define HD_  64
#define FF_  4096
#define NT   (B_*S_)
#define NEGV (-1e9f)

// ---------------- scratch -------------------------------------------------
__device__ int   g_kidx[B_*H_*S_];
__device__ int   g_kcnt[B_*H_];

__device__ __half g_wqkv16[3*D_*D_];
__device__ __half g_wo16  [D_*D_];
__device__ __half g_w116  [FF_*D_];
__device__ __half g_w216  [D_*FF_];
__device__ __half g_x16   [NT*D_];
__device__ __half g_qkv16 [NT*3*D_];
__device__ __half g_ctx16 [NT*D_];
__device__ __half g_h16   [NT*D_];
__device__ __half g_f116  [NT*FF_];
__device__ __half g_attn16[NT*D_];
__device__ __half g_f216  [NT*D_];

// ================= helpers =================================================
__device__ __forceinline__ uint32_t smem_u32(const void* p) {
    uint32_t a;
    asm("{ .reg .u64 t; cvta.to.shared.u64 t, %1; cvt.u32.u64 %0, t; }"
        : "=r"(a) : "l"(p));
    return a;
}
__device__ __forceinline__ void cp16(uint32_t dst, const void* src) {
    asm volatile("cp.async.cg.shared.global [%0], [%1], 16;" :: "r"(dst), "l"(src));
}
#define CP_COMMIT() asm volatile("cp.async.commit_group;" ::: "memory")
#define CP_WAIT1()  asm volatile("cp.async.wait_group 1;" ::: "memory")

#define LDSM4(r0,r1,r2,r3,addr) \
    asm volatile("ldmatrix.sync.aligned.m8n8.x4.shared.b16 {%0,%1,%2,%3}, [%4];" \
        : "=r"(r0), "=r"(r1), "=r"(r2), "=r"(r3) : "r"(addr))
#define LDSM4T(r0,r1,r2,r3,addr) \
    asm volatile("ldmatrix.sync.aligned.m8n8.x4.trans.shared.b16 {%0,%1,%2,%3}, [%4];" \
        : "=r"(r0), "=r"(r1), "=r"(r2), "=r"(r3) : "r"(addr))

__device__ __forceinline__ void mma_f16(
    float& d0, float& d1, float& d2, float& d3,
    uint32_t a0, uint32_t a1, uint32_t a2, uint32_t a3,
    uint32_t b0, uint32_t b1)
{
    asm volatile(
        "mma.sync.aligned.m16n8k16.row.col.f32.f16.f16.f32 "
        "{%0,%1,%2,%3}, {%4,%5,%6,%7}, {%8,%9}, {%0,%1,%2,%3};"
        : "+f"(d0), "+f"(d1), "+f"(d2), "+f"(d3)
        : "r"(a0), "r"(a1), "r"(a2), "r"(a3), "r"(b0), "r"(b1));
}

__device__ __forceinline__ uint32_t pack_h2(float a, float b) {
    __half2 h = __floats2half2_rn(a, b);
    return *(uint32_t*)&h;
}

// ---------------- fused fp32 -> fp16 convert -------------------------------
#define CVT_C0 (3*D_*D_)
#define CVT_C1 (CVT_C0 + D_*D_)
#define CVT_C2 (CVT_C1 + FF_*D_)
#define CVT_C3 (CVT_C2 + D_*FF_)
#define CVT_C4 (CVT_C3 + NT*D_)
#define CVT_BLOCKS (CVT_C4 / 4 / 256)

__global__ void __launch_bounds__(256) cvt_all_kernel(
    const float* __restrict__ Wqkv, const float* __restrict__ Wo,
    const float* __restrict__ W1,   const float* __restrict__ W2,
    const float* __restrict__ x,
    __half* __restrict__ wq16, __half* __restrict__ wo16,
    __half* __restrict__ w116, __half* __restrict__ w216,
    __half* __restrict__ x16)
{
    int i = (blockIdx.x * 256 + threadIdx.x) * 4;
    const float* in; __half* out; int base;
    if      (i < CVT_C0) { in = Wqkv; out = wq16; base = 0; }
    else if (i < CVT_C1) { in = Wo;   out = wo16; base = CVT_C0; }
    else if (i < CVT_C2) { in = W1;   out = w116; base = CVT_C1; }
    else if (i < CVT_C3) { in = W2;   out = w216; base = CVT_C2; }
    else                 { in = x;    out = x16;  base = CVT_C3; }
    i -= base;
    float4 v = *(const float4*)(in + i);
    *(uint32_t*)(out + i)     = pack_h2(v.x, v.y);
    *(uint32_t*)(out + i + 2) = pack_h2(v.z, v.w);
}

// ---------------- HMMA fp16 GEMM: C = A * B^T + bias -----------------------
// 128x128 CTA tile, BK=32, 256 threads (8 warps of 64x32), 2 CTAs/SM.
// 4-slot ring, prefetch distance 2, wait_group 1, barrier every 2 iters.
#define TSTRIDE   80
#define TMAT      (128 * TSTRIDE)
#define TSTAGE    (2 * TMAT)
#define GEMM_SMEM (4 * TSTAGE)

template<int RELU, int OUT>
__global__ void __launch_bounds__(256, 2) gemm_mma(
    const __half* __restrict__ A, const __half* __restrict__ Bm,
    const float* __restrict__ bias, float* __restrict__ C,
    __half* __restrict__ Ch,
    int M, int N, int K)
{
    extern __shared__ char smem[];
    const uint32_t sbase = smem_u32(smem);
    const int tid  = threadIdx.x;
    const int wid  = tid >> 5;
    const int lane = tid & 31;
    const int row0 = blockIdx.y * 128;
    const int col0 = blockIdx.x * 128;
    const int wm   = wid & 1;
    const int wn   = wid >> 1;

    const int l_mat = lane >> 3, l_r = lane & 7;
    const int frag_row = l_r + (l_mat & 1) * 8;
    const int frag_kb  = (l_mat >> 1) * 16;

    const int cp_row = tid >> 2;
    const int cp_c   = tid & 3;
    const __half* pA = A  + (size_t)(row0 + cp_row) * K + cp_c * 8;
    const __half* pB = Bm + (size_t)(col0 + cp_row) * K + cp_c * 8;
    const uint32_t sA0 = sbase + cp_row * TSTRIDE + cp_c * 16;
    const uint32_t sB0 = sA0 + TMAT;
    const size_t rstep = (size_t)64 * K;

    float acc[4][4][4];
    #pragma unroll
    for (int i = 0; i < 4; i++)
        #pragma unroll
        for (int j = 0; j < 4; j++)
            #pragma unroll
            for (int r = 0; r < 4; r++) acc[i][j][r] = 0.f;

    const int nstage = K >> 5;

    #pragma unroll
    for (int s = 0; s < 2; s++) {
        const uint32_t off = s * TSTAGE;
        const int k0 = s << 5;
        cp16(sA0 + off,                 pA + k0);
        cp16(sA0 + off + 64 * TSTRIDE,  pA + rstep + k0);
        cp16(sB0 + off,                 pB + k0);
        cp16(sB0 + off + 64 * TSTRIDE,  pB + rstep + k0);
        CP_COMMIT();
    }

    int slot = 0;
    int islot = 2;
    for (int s = 0; s < nstage; s++) {
        CP_WAIT1();
        if ((s & 1) == 0) __syncthreads();

        if (s + 2 < nstage) {
            const uint32_t off = islot * TSTAGE;
            const int k0 = (s + 2) << 5;
            cp16(sA0 + off,                pA + k0);
            cp16(sA0 + off + 64 * TSTRIDE, pA + rstep + k0);
            cp16(sB0 + off,                pB + k0);
            cp16(sB0 + off + 64 * TSTRIDE, pB + rstep + k0);
        }
        CP_COMMIT();

        const uint32_t buf = sbase + slot * TSTAGE;
        const uint32_t bA = buf;
        const uint32_t bB = buf + TMAT;

        #pragma unroll
        for (int ks = 0; ks < 2; ks++) {
            const int kb = ks * 32 + frag_kb;

            uint32_t a[4][4], b[2][4];
            #pragma unroll
            for (int mi = 0; mi < 4; mi++) {
                uint32_t ra = (wm * 64 + mi * 16 + frag_row) * TSTRIDE + kb;
                LDSM4(a[mi][0], a[mi][1], a[mi][2], a[mi][3], bA + ra);
            }
            #pragma unroll
            for (int nb = 0; nb < 2; nb++) {
                uint32_t rb = (wn * 32 + nb * 16 + frag_row) * TSTRIDE + kb;
                LDSM4(b[nb][0], b[nb][1], b[nb][2], b[nb][3], bB + rb);
            }

            #pragma unroll
            for (int mi = 0; mi < 4; mi++)
                #pragma unroll
                for (int ni = 0; ni < 4; ni++) {
                    const int nb = ni >> 1, no = ni & 1;
                    mma_f16(acc[mi][ni][0], acc[mi][ni][1],
                            acc[mi][ni][2], acc[mi][ni][3],
                            a[mi][0], a[mi][1], a[mi][2], a[mi][3],
                            b[nb][no], b[nb][no + 2]);
                }
        }
        slot  = (slot  + 1) & 3;
        islot = (islot + 1) & 3;
    }

    const int g8  = lane >> 2;
    const int tig = lane & 3;
    #pragma unroll
    for (int mi = 0; mi < 4; mi++) {
        #pragma unroll
        for (int ni = 0; ni < 4; ni++) {
            int col = col0 + wn * 32 + ni * 8 + tig * 2;
            float2 bs = *(const float2*)(bias + col);
            int r0 = row0 + wm * 64 + mi * 16 + g8;
            float2 v0 = { acc[mi][ni][0] + bs.x, acc[mi][ni][1] + bs.y };
            float2 v1 = { acc[mi][ni][2] + bs.x, acc[mi][ni][3] + bs.y };
            if (RELU) {
                v0.x = fmaxf(v0.x, 0.f); v0.y = fmaxf(v0.y, 0.f);
                v1.x = fmaxf(v1.x, 0.f); v1.y = fmaxf(v1.y, 0.f);
            }
            if (OUT == 0) {
                *(float2*)(C + (size_t)r0 * N + col)       = v0;
                *(float2*)(C + (size_t)(r0 + 8) * N + col) = v1;
            } else {
                *(uint32_t*)(Ch + (size_t)r0 * N + col)       = pack_h2(v0.x, v0.y);
                *(uint32_t*)(Ch + (size_t)(r0 + 8) * N + col) = pack_h2(v1.x, v1.y);
            }
        }
    }
}

// ---------------- mask compaction (with inline dtype probe) ----------------
__device__ __forceinline__ float mask_val_m(const void* mp, int idx, int mode) {
    if (mode == 0) return ((const int*)mp)[idx] ? 1.f : 0.f;
    if (mode == 1) return ((const unsigned char*)mp)[idx] ? 1.f : 0.f;
    return ((const float*)mp)[idx];
}

__global__ void __launch_bounds__(256) compact_mask_kernel(
    const void* __restrict__ mask, int* __restrict__ kidx,
    int* __restrict__ kcnt)
{
    const int bh  = blockIdx.x;
    const int tid = threadIdx.x;
    const int lane = tid & 31, wid = tid >> 5;
    __shared__ int wsum[8];
    __shared__ int stotal;
    __shared__ int smode;

    {
        __shared__ int f3f, foff;
        if (tid == 0) { f3f = 0; foff = 0; }
        __syncthreads();
        const unsigned char* m8 = (const unsigned char*)mask;
        int l3f = 0, loff = 0;
        for (int i = tid; i < 4096; i += 256) {
            unsigned char v = m8[i];
            if (v == 0x3f) l3f = 1;
            else if (v && (i & 3)) loff = 1;
        }
        if (l3f)  atomicOr(&f3f, 1);
        if (loff) atomicOr(&foff, 1);
        __syncthreads();
        if (tid == 0) smode = f3f ? 2 : (foff ? 1 : 0);
        __syncthreads();
    }
    const int mode = smode;

    int v[4], c = 0;
    #pragma unroll
    for (int j = 0; j < 4; j++) {
        v[j] = (mask_val_m(mask, bh * S_ + tid * 4 + j, mode) > 0.5f) ? 1 : 0;
        c += v[j];
    }
    int sc = c;
    #pragma unroll
    for (int o = 1; o < 32; o <<= 1) {
        int n = __shfl_up_sync(0xffffffffu, sc, o);
        if (lane >= o) sc += n;
    }
    if (lane == 31) wsum[wid] = sc;
    __syncthreads();
    if (tid == 0) {
        int acc = 0;
        #pragma unroll
        for (int i = 0; i < 8; i++) { int t = wsum[i]; wsum[i] = acc; acc += t; }
        stotal = acc;
    }
    __syncthreads();
    int off = sc - c + wsum[wid];
    #pragma unroll
    for (int j = 0; j < 4; j++)
        if (v[j]) kidx[bh * S_ + off++] = tid * 4 + j;
    int total = stotal;
    if (tid == 0) kcnt[bh] = total;
    for (int i = total + tid; i < S_; i += 256) kidx[bh * S_ + i] = 0;
}

// ---------------- flash attention (compacted keys, 3-stage pipeline) -------
#define ASTRIDE 144
#define KVMAT   (64 * ASTRIDE)
#define KVSTAGE (2 * KVMAT)
#define SMEM_ATTN (128 * ASTRIDE + 3 * KVSTAGE)
#define LOG2E_SC 0.18033688f

__device__ __forceinline__ void kv_prefetch(
    uint32_t sKV, int slot, int jb, int tid, int rowbase, int h,
    const __half* QKV, const int* __restrict__ idx)
{
    const uint32_t base = sKV + slot * KVSTAGE;
    const int r  = tid >> 2;
    const int c0 = tid & 3;
    const int token = __ldg(idx + jb * 64 + r);
    const size_t go = (size_t)(rowbase + token) * (3 * D_) + h * HD_;
    const __half* srcs[2] = { QKV + go + D_, QKV + go + 2 * D_ };
    #pragma unroll
    for (int m = 0; m < 2; m++) {
        const uint32_t mb = base + m * KVMAT + r * ASTRIDE;
        cp16(mb + c0 * 16,       srcs[m] + c0 * 8);
        cp16(mb + (c0 + 4) * 16, srcs[m] + (c0 + 4) * 8);
    }
}

__global__ void __launch_bounds__(256, 2) attn_mma_kernel(
    const __half* __restrict__ QKV,
    const int* __restrict__ kidx, const int* __restrict__ kcnt,
    __half* __restrict__ Cc)
{
    const int it = blockIdx.x, h = blockIdx.y, b = blockIdx.z;
    const int bh = b * H_ + h;
    extern __shared__ char sm8[];
    const uint32_t sb = smem_u32(sm8);
    const uint32_t sQ  = sb;
    const uint32_t sKV = sb + 128 * ASTRIDE;

    const int tid = threadIdx.x, w = tid >> 5, lane = tid & 31;
    const int i0 = it * 128, rowbase = b * S_;
    const int frag_row = (lane & 7) + ((lane >> 3) & 1) * 8;
    const int frag_kb  = (lane >> 4) * 16;
    const int pcol = (lane & 3) * 2;

    const int cnt = kcnt[bh];
    const int nt  = (cnt + 63) >> 6;
    const int* idx = kidx + bh * S_;

    {
        int r = tid >> 1;
        const size_t go = (size_t)(rowbase + i0 + r) * (3 * D_) + h * HD_;
        #pragma unroll
        for (int c = 0; c < 4; c++) {
            int ch = (tid & 1) * 4 + c;
            cp16(sQ + r * ASTRIDE + ch * 16, QKV + go + ch * 8);
        }
    }
    kv_prefetch(sKV, 0, 0, tid, rowbase, h, QKV, idx);
    CP_COMMIT();
    if (nt > 1) kv_prefetch(sKV, 1, 1, tid, rowbase, h, QKV, idx);
    CP_COMMIT();

    // hoisted fragment base addresses (constant across jb)
    uint32_t qaddr[4], kaddr0[4];
    #pragma unroll
    for (int kk = 0; kk < 4; kk++) {
        qaddr[kk]  = sQ + (w * 16 + frag_row) * ASTRIDE + kk * 32 + frag_kb;
        kaddr0[kk] = (uint32_t)(frag_row * ASTRIDE + kk * 32 + frag_kb);
    }

    float m_run[2] = { -3.0e38f, -3.0e38f };
    float l_run[2] = { 0.f, 0.f };
    float o[8][4];
    #pragma unroll
    for (int d = 0; d < 8; d++)
        #pragma unroll
        for (int r = 0; r < 4; r++) o[d][r] = 0.f;

    int slot = 0, islot = 2;
    for (int jb = 0; jb < nt; jb++) {
        CP_WAIT1();
        __syncthreads();

        if (jb + 2 < nt)
            kv_prefetch(sKV, islot, jb + 2, tid, rowbase, h, QKV, idx);
        CP_COMMIT();

        const uint32_t kvb = sKV + slot * KVSTAGE;
        const uint32_t bK = kvb, bV = kvb + KVMAT;

        float s[8][4];
        #pragma unroll
        for (int t = 0; t < 8; t++)
            #pragma unroll
            for (int r = 0; r < 4; r++) s[t][r] = 0.f;

        #pragma unroll
        for (int kk = 0; kk < 4; kk++) {
            uint32_t q0, q1, q2, q3;
            LDSM4(q0, q1, q2, q3, qaddr[kk]);
            #pragma unroll
            for (int nb = 0; nb < 4; nb++) {
                uint32_t k0, k1, k2, k3;
                LDSM4(k0, k1, k2, k3, bK + kaddr0[kk] + nb * 16 * ASTRIDE);
                const int t0 = nb * 2, t1 = nb * 2 + 1;
                mma_f16(s[t0][0], s[t0][1], s[t0][2], s[t0][3],
                        q0, q1, q2, q3, k0, k2);
                mma_f16(s[t1][0], s[t1][1], s[t1][2], s[t1][3],
                        q0, q1, q2, q3, k1, k3);
            }
        }

        // ---- scale (+ tail-only validity masking) ----
        if ((jb + 1) * 64 <= cnt) {
            // full tile: all keys valid (common path, no compares)
            #pragma unroll
            for (int t = 0; t < 8; t++) {
                s[t][0] *= LOG2E_SC; s[t][1] *= LOG2E_SC;
                s[t][2] *= LOG2E_SC; s[t][3] *= LOG2E_SC;
            }
        } else {
            #pragma unroll
            for (int t = 0; t < 8; t++) {
                int p = jb * 64 + t * 8 + pcol;
                bool v0 = p < cnt, v1 = p + 1 < cnt;
                s[t][0] = v0 ? s[t][0] * LOG2E_SC : NEGV;
                s[t][1] = v1 ? s[t][1] * LOG2E_SC : NEGV;
                s[t][2] = v0 ? s[t][2] * LOG2E_SC : NEGV;
                s[t][3] = v1 ? s[t][3] * LOG2E_SC : NEGV;
            }
        }

        float mx0 = -3.0e38f, mx1 = -3.0e38f;
        #pragma unroll
        for (int t = 0; t < 8; t++) {
            mx0 = fmaxf(mx0, fmaxf(s[t][0], s[t][1]));
            mx1 = fmaxf(mx1, fmaxf(s[t][2], s[t][3]));
        }
        mx0 = fmaxf(mx0, __shfl_xor_sync(0xffffffffu, mx0, 1));
        mx0 = fmaxf(mx0, __shfl_xor_sync(0xffffffffu, mx0, 2));
        mx1 = fmaxf(mx1, __shfl_xor_sync(0xffffffffu, mx1, 1));
        mx1 = fmaxf(mx1, __shfl_xor_sync(0xffffffffu, mx1, 2));
        float nm0 = fmaxf(m_run[0], mx0), nm1 = fmaxf(m_run[1], mx1);
        float corr0 = exp2f(m_run[0] - nm0), corr1 = exp2f(m_run[1] - nm1);
        m_run[0] = nm0; m_run[1] = nm1;

        float sum0 = 0.f, sum1 = 0.f;
        #pragma unroll
        for (int t = 0; t < 8; t++) {
            s[t][0] = exp2f(s[t][0] - nm0); sum0 += s[t][0];
            s[t][1] = exp2f(s[t][1] - nm0); sum0 += s[t][1];
            s[t][2] = exp2f(s[t][2] - nm1); sum1 += s[t][2];
            s[t][3] = exp2f(s[t][3] - nm1); sum1 += s[t][3];
        }
        sum0 += __shfl_xor_sync(0xffffffffu, sum0, 1);
        sum0 += __shfl_xor_sync(0xffffffffu, sum0, 2);
        sum1 += __shfl_xor_sync(0xffffffffu, sum1, 1);
        sum1 += __shfl_xor_sync(0xffffffffu, sum1, 2);
        l_run[0] = l_run[0] * corr0 + sum0;
        l_run[1] = l_run[1] * corr1 + sum1;

        #pragma unroll
        for (int d = 0; d < 8; d++) {
            o[d][0] *= corr0; o[d][1] *= corr0;
            o[d][2] *= corr1; o[d][3] *= corr1;
        }

        #pragma unroll
        for (int kk = 0; kk < 4; kk++) {
            const int t0 = kk * 2, t1 = kk * 2 + 1;
            uint32_t pa[4];
            pa[0] = pack_h2(s[t0][0], s[t0][1]);
            pa[1] = pack_h2(s[t0][2], s[t0][3]);
            pa[2] = pack_h2(s[t1][0], s[t1][1]);
            pa[3] = pack_h2(s[t1][2], s[t1][3]);

            const uint32_t vrow =
                (kk * 16 + ((lane >> 3) & 1) * 8 + (lane & 7)) * ASTRIDE +
                (lane >> 4) * 16;
            #pragma unroll
            for (int qd = 0; qd < 4; qd++) {
                uint32_t v0, v1, v2, v3;
                LDSM4T(v0, v1, v2, v3, bV + vrow + qd * 32);
                const int d0 = qd * 2, d1 = qd * 2 + 1;
                mma_f16(o[d0][0], o[d0][1], o[d0][2], o[d0][3],
                        pa[0], pa[1], pa[2], pa[3], v0, v1);
                mma_f16(o[d1][0], o[d1][1], o[d1][2], o[d1][3],
                        pa[0], pa[1], pa[2], pa[3], v2, v3);
            }
        }
        slot  = (slot  == 2) ? 0 : slot + 1;
        islot = (islot == 2) ? 0 : islot + 1;
    }

    const float inv0 = 1.f / l_run[0], inv1 = 1.f / l_run[1];
    const int tok0 = rowbase + i0 + w * 16 + (lane >> 2);
    #pragma unroll
    for (int d = 0; d < 8; d++) {
        int col = h * HD_ + d * 8 + (lane & 3) * 2;
        *(uint32_t*)(Cc + (size_t)tok0 * D_ + col) =
            pack_h2(o[d][0] * inv0, o[d][1] * inv0);
        *(uint32_t*)(Cc + (size_t)(tok0 + 8) * D_ + col) =
            pack_h2(o[d][2] * inv1, o[d][3] * inv1);
    }
}

// ---------------- residual + LayerNorm (all-fp16 in; fp16 or fp32 out) -----
template<int OUTF32>
__global__ void __launch_bounds__(256) ln_residual_kernel(
    const __half* __restrict__ a, const __half* __restrict__ res,
    const float* __restrict__ gamma, const float* __restrict__ beta,
    float* __restrict__ out, __half* __restrict__ oh)
{
    const int row = blockIdx.x;
    const int tid = threadIdx.x;
    const __half* pa = a   + (size_t)row * D_ + tid * 4;
    const __half* pr = res + (size_t)row * D_ + tid * 4;

    __half2 a01 = *(const __half2*)(pa);
    __half2 a23 = *(const __half2*)(pa + 2);
    __half2 r01 = *(const __half2*)(pr);
    __half2 r23 = *(const __half2*)(pr + 2);
    float v[4];
    v[0] = __half2float(__low2half(a01))  + __half2float(__low2half(r01));
    v[1] = __half2float(__high2half(a01)) + __half2float(__high2half(r01));
    v[2] = __half2float(__low2half(a23))  + __half2float(__low2half(r23));
    v[3] = __half2float(__high2half(a23)) + __half2float(__high2half(r23));

    float sum = v[0] + v[1] + v[2] + v[3];
    float sq  = v[0]*v[0] + v[1]*v[1] + v[2]*v[2] + v[3]*v[3];
    #pragma unroll
    for (int o2 = 16; o2; o2 >>= 1) {
        sum += __shfl_xor_sync(0xffffffffu, sum, o2);
        sq  += __shfl_xor_sync(0xffffffffu, sq,  o2);
    }
    __shared__ float sh1[8], sh2[8];
    __shared__ float smean, srstd;
    if ((tid & 31) == 0) { sh1[tid >> 5] = sum; sh2[tid >> 5] = sq; }
    __syncthreads();
    if (tid == 0) {
        float s = 0.f, s2 = 0.f;
        #pragma unroll
        for (int i = 0; i < 8; i++) { s += sh1[i]; s2 += sh2[i]; }
        float mean = s * (1.f / D_);
        float var  = s2 * (1.f / D_) - mean * mean;
        smean = mean;
        srstd = rsqrtf(var + 1e-12f);
    }
    __syncthreads();
    float mean = smean, rstd = srstd;
    const int c0 = tid * 4;
    float4 gm = *(const float4*)(gamma + c0);
    float4 bt = *(const float4*)(beta + c0);
    float r0 = gm.x * (v[0] - mean) * rstd + bt.x;
    float r1 = gm.y * (v[1] - mean) * rstd + bt.y;
    float r2 = gm.z * (v[2] - mean) * rstd + bt.z;
    float r3 = gm.w * (v[3] - mean) * rstd + bt.w;
    if (OUTF32) {
        float4 o4 = { r0, r1, r2, r3 };
        *(float4*)(out + (size_t)row * D_ + c0) = o4;
    } else {
        *(uint32_t*)(oh + (size_t)row * D_ + c0)     = pack_h2(r0, r1);
        *(uint32_t*)(oh + (size_t)row * D_ + c0 + 2) = pack_h2(r2, r3);
    }
}

// ---------------- launch ---------------------------------------------------
extern "C" void kernel_launch(void* const* d_in, const int* in_sizes, int n_in,
                              void* d_out, int out_size)
{
    const float* x    = (const float*)d_in[0];
    const void*  mask = d_in[1];
    const float* Wqkv = (const float*)d_in[2];
    const float* bqkv = (const float*)d_in[3];
    const float* Wo   = (const float*)d_in[4];
    const float* bo   = (const float*)d_in[5];
    const float* W1   = (const float*)d_in[6];
    const float* b1   = (const float*)d_in[7];
    const float* W2   = (const float*)d_in[8];
    const float* b2   = (const float*)d_in[9];
    const float* g1   = (const float*)d_in[10];
    const float* be1  = (const float*)d_in[11];
    const float* g2   = (const float*)d_in[12];
    const float* be2  = (const float*)d_in[13];
    float* out = (float*)d_out;

    int *kidx, *kcnt;
    cudaGetSymbolAddress((void**)&kidx, g_kidx);
    cudaGetSymbolAddress((void**)&kcnt, g_kcnt);

    __half *wq16, *wo16, *w116, *w216, *x16, *qkv16, *ctx16, *h16, *f116;
    __half *attn16, *f216;
    cudaGetSymbolAddress((void**)&wq16, g_wqkv16);
    cudaGetSymbolAddress((void**)&wo16, g_wo16);
    cudaGetSymbolAddress((void**)&w116, g_w116);
    cudaGetSymbolAddress((void**)&w216, g_w216);
    cudaGetSymbolAddress((void**)&x16,  g_x16);
    cudaGetSymbolAddress((void**)&qkv16, g_qkv16);
    cudaGetSymbolAddress((void**)&ctx16, g_ctx16);
    cudaGetSymbolAddress((void**)&h16,  g_h16);
    cudaGetSymbolAddress((void**)&f116, g_f116);
    cudaGetSymbolAddress((void**)&attn16, g_attn16);
    cudaGetSymbolAddress((void**)&f216, g_f216);

    cudaFuncSetAttribute(attn_mma_kernel,
                         cudaFuncAttributeMaxDynamicSharedMemorySize, SMEM_ATTN);
    cudaFuncSetAttribute(gemm_mma<0,1>,
                         cudaFuncAttributeMaxDynamicSharedMemorySize, GEMM_SMEM);
    cudaFuncSetAttribute(gemm_mma<1,1>,
                         cudaFuncAttributeMaxDynamicSharedMemorySize, GEMM_SMEM);

    // 1: per-(b,h) key compaction (with inline dtype probe)
    compact_mask_kernel<<<B_ * H_, 256>>>(mask, kidx, kcnt);

    // 2: all converts in one launch
    cvt_all_kernel<<<CVT_BLOCKS, 256>>>(Wqkv, Wo, W1, W2, x,
                                        wq16, wo16, w116, w216, x16);

    // 3: qkv = x @ Wqkv^T + bqkv -> fp16
    gemm_mma<0,1><<<dim3(3 * D_ / 128, NT / 128), 256, GEMM_SMEM>>>(
        x16, wq16, bqkv, nullptr, qkv16, NT, 3 * D_, D_);

    // 4: attention over compacted keys -> ctx fp16
    attn_mma_kernel<<<dim3(S_ / 128, H_, B_), 256, SMEM_ATTN>>>(
        qkv16, kidx, kcnt, ctx16);

    // 5: attn_out = ctx @ Wo^T + bo -> fp16
    gemm_mma<0,1><<<dim3(D_ / 128, NT / 128), 256, GEMM_SMEM>>>(
        ctx16, wo16, bo, nullptr, attn16, NT, D_, D_);

    // 6: h = LN1(attn_out + x) -> fp16 only
    ln_residual_kernel<0><<<NT, 256>>>(attn16, x16, g1, be1, nullptr, h16);

    // 7: f1 = relu(h @ W1^T + b1) -> fp16
    gemm_mma<1,1><<<dim3(FF_ / 128, NT / 128), 256, GEMM_SMEM>>>(
        h16, w116, b1, nullptr, f116, NT, FF_, D_);

    // 8: f2 = f1 @ W2^T + b2 -> fp16
    gemm_mma<0,1><<<dim3(D_ / 128, NT / 128), 256, GEMM_SMEM>>>(
        f116, w216, b2, nullptr, f216, NT, D_, FF_);

    // 9: out = LN2(f2 + h) -> fp32
    ln_residual_kernel<1><<<NT, 256>>>(f216, h16, g2, be2, out, nullptr);
}